// round 16
// baseline (speedup 1.0000x reference)
#include <cuda_runtime.h>
#include <cuda_bf16.h>
#include <math.h>
#include <cstdint>

// Problem constants
#define NSRC 4000
#define NTGT 4096
#define TOFF 4096            // target tower row offset in merged node space
#define NROW 8192            // merged rows (4096 + 4096)
#define DIN 128
#define DH 256
#define CATW 896             // 128 + 3*256
#define ALPHA_C 20.0f
#define EPS_C 1e-10f
#define CAP 128              // per-node neighbor-list capacity (P(deg>128) ~ 1e-60)

// ================= generic-PTX helpers (sm_80+; NO tcgen05/arch-a) =================
__device__ __forceinline__ uint32_t smem_to_u32(const void* smem_ptr) {
    uint32_t addr;
    asm("{ .reg .u64 tmp; cvta.to.shared.u64 tmp, %1; cvt.u32.u64 %0, tmp; }"
        : "=r"(addr) : "l"(smem_ptr));
    return addr;
}
__device__ __forceinline__ void ldm_x4(uint32_t* r, uint32_t addr) {
    asm volatile("ldmatrix.sync.aligned.m8n8.x4.shared.b16 {%0,%1,%2,%3}, [%4];"
        : "=r"(r[0]), "=r"(r[1]), "=r"(r[2]), "=r"(r[3]) : "r"(addr));
}
__device__ __forceinline__ void mma16816(float* d, const uint32_t* a, const uint32_t* b) {
    asm volatile(
        "mma.sync.aligned.m16n8k16.row.col.f32.bf16.bf16.f32 "
        "{%0,%1,%2,%3}, {%4,%5,%6,%7}, {%8,%9}, {%0,%1,%2,%3};"
        : "+f"(d[0]), "+f"(d[1]), "+f"(d[2]), "+f"(d[3])
        : "r"(a[0]), "r"(a[1]), "r"(a[2]), "r"(a[3]), "r"(b[0]), "r"(b[1]));
}
__device__ __forceinline__ void cpa16(uint32_t saddr, const void* g) {
    asm volatile("cp.async.cg.shared.global [%0], [%1], 16;" :: "r"(saddr), "l"(g));
}
#define CP_COMMIT() asm volatile("cp.async.commit_group;" ::: "memory")
#define CP_WAIT1()  asm volatile("cp.async.wait_group 1;" ::: "memory")
#define CP_WAIT0()  asm volatile("cp.async.wait_group 0;" ::: "memory")
__device__ __forceinline__ uint32_t pack_bf2(__nv_bfloat16 a, __nv_bfloat16 b) {
    __nv_bfloat162 t = __halves2bfloat162(a, b);
    return *(uint32_t*)&t;
}
__device__ __forceinline__ void split1(float v, __nv_bfloat16& h, __nv_bfloat16& l) {
    h = __float2bfloat16(v);
    l = __float2bfloat16(v - __bfloat162float(h));
}

// ---------------- device scratch (static, no allocation) ----------------
__device__ __align__(128) float g_cat[(size_t)NROW * CATW];                 // fp32 concat features
__device__ __align__(128) __nv_bfloat16 g_cat_hi[(size_t)NROW * CATW];
__device__ __align__(128) __nv_bfloat16 g_cat_lo[(size_t)NROW * CATW];
__device__ __align__(128) __nv_bfloat16 g_hc_hi[(size_t)NROW * 768];
__device__ __align__(128) __nv_bfloat16 g_hc_lo[(size_t)NROW * 768];
__device__ __align__(128) float g_feat[(size_t)NROW * DH];
__device__ __align__(128) __nv_bfloat16 g_ft_hi[(size_t)NROW * DH];
__device__ __align__(128) __nv_bfloat16 g_ft_lo[(size_t)NROW * DH];
__device__ __align__(128) __nv_bfloat16 g_wt_hi[720896];                    // [256 x fan3] K-major
__device__ __align__(128) __nv_bfloat16 g_wt_lo[720896];
__device__ __align__(128) float g_S0[(size_t)NTGT * NTGT];                  // 64MB
__device__ __align__(128) float g_cs[5 * NTGT];                             // colsum buffers
__device__ __align__(128) float g_rcd[NROW];
__device__ __align__(128) float g_rcs[NROW];
__device__ __align__(128) int g_incnt[NROW];
__device__ __align__(128) int g_outcnt[NROW];
__device__ __align__(128) int g_inlist[(size_t)NROW * CAP];
__device__ __align__(128) int g_outlist[(size_t)NROW * CAP];

// ---------------- weight packing: transposed + split [256 x fan3] ----------------
__global__ void pack_wt_kernel(const float* __restrict__ W1_0, const float* __restrict__ W2_0, const float* __restrict__ Wr_0,
                               const float* __restrict__ W1_1, const float* __restrict__ W2_1, const float* __restrict__ Wr_1,
                               const float* __restrict__ W1_2, const float* __restrict__ W2_2, const float* __restrict__ Wr_2,
                               const float* __restrict__ final_w)
{
    int g = blockIdx.x * 256 + threadIdx.x;
    if (g >= 720896) return;
    float v;
    if (g < 98304) {
        int n = g / 384, k = g - n * 384;
        int sub = k >> 7, kr = k & 127;
        const float* s = (sub == 0) ? Wr_0 : ((sub == 1) ? W1_0 : W2_0);
        v = s[kr * 256 + n];
    } else if (g < 294912) {
        int g2 = g - 98304;
        int n = g2 / 768, k = g2 - n * 768;
        int sub = k >> 8, kr = k & 255;
        const float* s = (sub == 0) ? Wr_1 : ((sub == 1) ? W1_1 : W2_1);
        v = s[kr * 256 + n];
    } else if (g < 491520) {
        int g2 = g - 294912;
        int n = g2 / 768, k = g2 - n * 768;
        int sub = k >> 8, kr = k & 255;
        const float* s = (sub == 0) ? Wr_2 : ((sub == 1) ? W1_2 : W2_2);
        v = s[kr * 256 + n];
    } else {
        int g2 = g - 491520;
        int n = g2 / 896, k = g2 - n * 896;
        v = final_w[k * 256 + n];
    }
    __nv_bfloat16 h, l; split1(v, h, l);
    g_wt_hi[g] = h; g_wt_lo[g] = l;
}

// ---------------- init: zero degree counters + colsum buffers ----------------
__global__ void init_kernel()
{
    int i = blockIdx.x * 256 + threadIdx.x;
    if (i < NROW) { g_incnt[i] = 0; g_outcnt[i] = 0; }
    if (i < NTGT) {
#pragma unroll
        for (int b = 0; b < 5; b++) g_cs[b * NTGT + i] = 0.f;
    }
}

// ---------------- fill fixed-capacity adjacency lists ----------------
__global__ void fill_kernel(const int* __restrict__ es_s, const int* __restrict__ ed_s, int Es,
                            const int* __restrict__ es_t, const int* __restrict__ ed_t, int Et)
{
    int e = blockIdx.x * 256 + threadIdx.x;
    if (e >= Es + Et) return;
    int s, d;
    if (e < Es) { s = es_s[e]; d = ed_s[e]; }
    else { int e2 = e - Es; s = es_t[e2] + TOFF; d = ed_t[e2] + TOFF; }
    int sl = atomicAdd(&g_incnt[d], 1);
    if (sl < CAP) g_inlist[(size_t)d * CAP + sl] = s;
    int sl2 = atomicAdd(&g_outcnt[s], 1);
    if (sl2 < CAP) g_outlist[(size_t)s * CAP + sl2] = d;
}

__global__ void recip_kernel()
{
    int i = blockIdx.x * 256 + threadIdx.x;
    if (i < NROW) {
        g_rcd[i] = 1.f / fmaxf((float)g_incnt[i], 1.f);
        g_rcs[i] = 1.f / fmaxf((float)g_outcnt[i], 1.f);
    }
}

// ---------------- layer 0 gather: root=x, agg via lists, write hc hi/lo + cat hi/lo ----------------
__global__ __launch_bounds__(256, 1) void gather0_kernel(const float* __restrict__ xs, const float* __restrict__ xt)
{
    __shared__ int lists[2][2][CAP];
    __shared__ int cnts[2][2];
    int tid = threadIdx.x;
    int half = tid >> 7;
    int col = tid & 127;
    int node = blockIdx.x * 2 + half;
    if (col == 0) {
        cnts[half][0] = min(g_incnt[node], CAP);
        cnts[half][1] = min(g_outcnt[node], CAP);
    }
    __syncthreads();
    int ic = cnts[half][0], oc = cnts[half][1];
    if (col < ic) lists[half][0][col] = g_inlist[(size_t)node * CAP + col];
    if (col < oc) lists[half][1][col] = g_outlist[(size_t)node * CAP + col];
    __syncthreads();

    float root = 0.f;
    if (node < NSRC) root = xs[(size_t)node * 128 + col];
    else if (node >= TOFF) root = xt[(size_t)(node - TOFF) * 128 + col];

    float a1 = 0.f, a2 = 0.f;
#pragma unroll 4
    for (int i = 0; i < ic; i++) {
        int nb = lists[half][0][i];
        float hv = (nb < NSRC) ? xs[(size_t)nb * 128 + col]
                 : ((nb >= TOFF) ? xt[(size_t)(nb - TOFF) * 128 + col] : 0.f);
        a1 += hv;
    }
#pragma unroll 4
    for (int i = 0; i < oc; i++) {
        int nb = lists[half][1][i];
        float hv = (nb < NSRC) ? xs[(size_t)nb * 128 + col]
                 : ((nb >= TOFF) ? xt[(size_t)(nb - TOFF) * 128 + col] : 0.f);
        a2 += hv;
    }
    a1 *= g_rcd[node];
    a2 *= g_rcs[node];

    size_t o = (size_t)node * 384;
    __nv_bfloat16 h, l;
    split1(root, h, l);
    g_hc_hi[o + col] = h; g_hc_lo[o + col] = l;
    size_t oc2 = (size_t)node * CATW + col;
    g_cat[oc2] = root;
    g_cat_hi[oc2] = h; g_cat_lo[oc2] = l;
    split1(a1, h, l);
    g_hc_hi[o + 128 + col] = h; g_hc_lo[o + 128 + col] = l;
    split1(a2, h, l);
    g_hc_hi[o + 256 + col] = h; g_hc_lo[o + 256 + col] = l;
}

// ---------------- layers 1-2 gather: root = cat column block (fan=256) ----------------
__global__ __launch_bounds__(256, 1) void gather12_kernel(const float* __restrict__ h)
{
    __shared__ int lin[CAP], lout[CAP];
    __shared__ int sc[2];
    int col = threadIdx.x;
    int node = blockIdx.x;
    if (col == 0) {
        sc[0] = min(g_incnt[node], CAP);
        sc[1] = min(g_outcnt[node], CAP);
    }
    __syncthreads();
    int ic = sc[0], oc = sc[1];
    if (col < ic) lin[col] = g_inlist[(size_t)node * CAP + col];
    if (col < oc) lout[col] = g_outlist[(size_t)node * CAP + col];
    __syncthreads();

    float root = h[(size_t)node * CATW + col];
    float a1 = 0.f, a2 = 0.f;
#pragma unroll 4
    for (int i = 0; i < ic; i++) a1 += h[(size_t)lin[i] * CATW + col];
#pragma unroll 4
    for (int i = 0; i < oc; i++) a2 += h[(size_t)lout[i] * CATW + col];
    a1 *= g_rcd[node];
    a2 *= g_rcs[node];

    size_t o = (size_t)node * 768;
    __nv_bfloat16 hh, ll;
    split1(root, hh, ll);
    g_hc_hi[o + col] = hh; g_hc_lo[o + col] = ll;
    split1(a1, hh, ll);
    g_hc_hi[o + 256 + col] = hh; g_hc_lo[o + 256 + col] = ll;
    split1(a2, hh, ll);
    g_hc_hi[o + 512 + col] = hh; g_hc_lo[o + 512 + col] = ll;
}

// ================= HMMA bf16-split GEMM, cp.async 2-stage =================
// CTA = 128x128, 8 warps 4x2, warp 32x64. 3 passes Ah*Bh + Ah*Bl + Al*Bh.
// EPI: 0 = bias+relu, write C fp32 + Chi/Clo bf16 ; 1 = bias, C fp32 ; 2 = exp + colsum into cs0
#define PAD 40                      // bf16/row in smem (80B stride, conflict-free ldmatrix)
#define TILE_B 10240                // 128*PAD*2 bytes
#define SMEM_GEMM (2*4*TILE_B + 512)

template<int EPI>
__global__ __launch_bounds__(256, 1) void gemm_kernel(
    const __nv_bfloat16* __restrict__ Ahi, const __nv_bfloat16* __restrict__ Alo, int lda,
    const __nv_bfloat16* __restrict__ Bhi, const __nv_bfloat16* __restrict__ Blo, int ldb,
    int K, const float* __restrict__ bias,
    float* __restrict__ C, __nv_bfloat16* __restrict__ Chi, __nv_bfloat16* __restrict__ Clo,
    int ldc, float* __restrict__ cs0)
{
    extern __shared__ char smem[];
    const uint32_t sb = smem_to_u32(smem);
    const int tid = threadIdx.x, wid = tid >> 5, lid = tid & 31;
    const int m0 = blockIdx.x * 128, n0 = blockIdx.y * 128;
    const int wm = (wid >> 1) * 32, wn = (wid & 1) * 64;

    const int nk = K >> 5;
    float acc[2][8][4] = {};

    // prefetch stage 0
    {
#pragma unroll
        for (int i = 0; i < 2; i++) {
            int q = tid + i * 256;
            int r = q >> 2, cc = (q & 3) << 3;
            uint32_t so = r * 80 + cc * 2;
            size_t ga = (size_t)(m0 + r) * lda + cc;
            size_t gb = (size_t)(n0 + r) * ldb + cc;
            cpa16(sb + 0 * TILE_B + so, Ahi + ga);
            cpa16(sb + 1 * TILE_B + so, Alo + ga);
            cpa16(sb + 2 * TILE_B + so, Bhi + gb);
            cpa16(sb + 3 * TILE_B + so, Blo + gb);
        }
        CP_COMMIT();
    }

    for (int kt = 0; kt < nk; kt++) {
        if (kt + 1 < nk) {
            uint32_t st = ((kt + 1) & 1) * 4 * TILE_B;
            int k0 = (kt + 1) << 5;
#pragma unroll
            for (int i = 0; i < 2; i++) {
                int q = tid + i * 256;
                int r = q >> 2, cc = (q & 3) << 3;
                uint32_t so = r * 80 + cc * 2;
                size_t ga = (size_t)(m0 + r) * lda + k0 + cc;
                size_t gb = (size_t)(n0 + r) * ldb + k0 + cc;
                cpa16(sb + st + 0 * TILE_B + so, Ahi + ga);
                cpa16(sb + st + 1 * TILE_B + so, Alo + ga);
                cpa16(sb + st + 2 * TILE_B + so, Bhi + gb);
                cpa16(sb + st + 3 * TILE_B + so, Blo + gb);
            }
            CP_COMMIT();
            CP_WAIT1();
        } else {
            CP_WAIT0();
        }
        __syncthreads();

        const uint32_t base = sb + (kt & 1) * 4 * TILE_B;
        const uint32_t uAh = base, uAl = base + TILE_B, uBh = base + 2 * TILE_B, uBl = base + 3 * TILE_B;
#pragma unroll
        for (int kk = 0; kk < 32; kk += 16) {
            uint32_t ah[2][4], al[2][4], bh[4][4], bl[4][4];
#pragma unroll
            for (int mt = 0; mt < 2; mt++) {
                uint32_t row = wm + mt * 16 + (lid & 15);
                uint32_t col = kk + ((lid & 16) >> 1);
                uint32_t off = row * 80 + col * 2;
                ldm_x4(ah[mt], uAh + off);
                ldm_x4(al[mt], uAl + off);
            }
#pragma unroll
            for (int p = 0; p < 4; p++) {
                uint32_t row = wn + p * 16 + (lid & 7) + ((lid & 16) >> 1);
                uint32_t col = kk + (lid & 8);
                uint32_t off = row * 80 + col * 2;
                ldm_x4(bh[p], uBh + off);
                ldm_x4(bl[p], uBl + off);
            }
#pragma unroll
            for (int mt = 0; mt < 2; mt++)
#pragma unroll
                for (int nt = 0; nt < 8; nt++) {
                    const uint32_t* bhp = &bh[nt >> 1][(nt & 1) << 1];
                    const uint32_t* blp = &bl[nt >> 1][(nt & 1) << 1];
                    mma16816(acc[mt][nt], ah[mt], bhp);
                    mma16816(acc[mt][nt], ah[mt], blp);
                    mma16816(acc[mt][nt], al[mt], bhp);
                }
        }
        __syncthreads();
    }

    // ---- epilogue ----
    const int g = lid >> 2, t2 = (lid & 3) << 1;
    float* scol = (float*)(smem + 8 * TILE_B);
    float csl[16];
    if (EPI == 2) {
        if (tid < 128) scol[tid] = 0.f;
#pragma unroll
        for (int i = 0; i < 16; i++) csl[i] = 0.f;
        __syncthreads();
    }
#pragma unroll
    for (int mt = 0; mt < 2; mt++) {
        int r0 = m0 + wm + mt * 16 + g;
#pragma unroll
        for (int nt = 0; nt < 8; nt++) {
            int col = n0 + wn + nt * 8 + t2;
            float* a = acc[mt][nt];
            float b0 = 0.f, b1 = 0.f;
            if (EPI < 2) { b0 = __ldg(&bias[col]); b1 = __ldg(&bias[col + 1]); }
#pragma unroll
            for (int hrow = 0; hrow < 2; hrow++) {
                int row = r0 + hrow * 8;
                float vx = a[hrow * 2 + 0], vy = a[hrow * 2 + 1];
                if (EPI == 2) {
                    vx = __expf(ALPHA_C * (vx + EPS_C));
                    vy = __expf(ALPHA_C * (vy + EPS_C));
                    csl[nt * 2 + 0] += vx;
                    csl[nt * 2 + 1] += vy;
                    *(float2*)&C[(size_t)row * ldc + col] = make_float2(vx, vy);
                } else {
                    vx += b0; vy += b1;
                    if (EPI == 0) { vx = fmaxf(vx, 0.f); vy = fmaxf(vy, 0.f); }
                    *(float2*)&C[(size_t)row * ldc + col] = make_float2(vx, vy);
                    if (EPI == 0) {
                        __nv_bfloat16 h0, l0, h1, l1;
                        split1(vx, h0, l0); split1(vy, h1, l1);
                        *(uint32_t*)&Chi[(size_t)row * ldc + col] = pack_bf2(h0, h1);
                        *(uint32_t*)&Clo[(size_t)row * ldc + col] = pack_bf2(l0, l1);
                    }
                }
            }
        }
    }
    if (EPI == 2) {
#pragma unroll
        for (int nt = 0; nt < 8; nt++) {
            atomicAdd(&scol[wn + nt * 8 + t2 + 0], csl[nt * 2 + 0]);
            atomicAdd(&scol[wn + nt * 8 + t2 + 1], csl[nt * 2 + 1]);
        }
        __syncthreads();
        if (tid < 128) atomicAdd(&cs0[n0 + tid], scol[tid]);
    }
}

// ---------------- l2 normalize + split to bf16 (gap rows zeroed) ----------------
__global__ void l2norm_split_kernel()
{
    int row = blockIdx.x, t = threadIdx.x;
    bool gap = (row >= NSRC && row < TOFF);
    float v = gap ? 0.f : g_feat[(size_t)row * 256 + t];
    float s = v * v;
#pragma unroll
    for (int o = 16; o; o >>= 1) s += __shfl_xor_sync(0xffffffffu, s, o);
    __shared__ float sm[8];
    int w = t >> 5;
    if ((t & 31) == 0) sm[w] = s;
    __syncthreads();
    if (t < 8) {
        float tot = sm[t];
#pragma unroll
        for (int o = 4; o; o >>= 1) tot += __shfl_xor_sync(0xffu, tot, o);
        if (t == 0) sm[0] = tot;
    }
    __syncthreads();
    float scale = 1.f / fmaxf(sqrtf(sm[0]), 1e-12f);
    float o = v * scale;
    __nv_bfloat16 h, l; split1(o, h, l);
    g_ft_hi[(size_t)row * 256 + t] = h;
    g_ft_lo[(size_t)row * 256 + t] = l;
}

// ---------------- fused sinkhorn row+col pass (single S0 read, 4 rows/block) ----------------
// pass1: u_r = 1/sum_j S0[r][j]/cs[j]; pass2 (cached): csn[j] += sum_r u_r*S0[r][j].
__global__ __launch_bounds__(256, 1) void sink_rowcol_kernel(
    const float* __restrict__ cs, float* __restrict__ csn, const float* __restrict__ S0)
{
    int r0 = blockIdx.x * 4, t = threadIdx.x;
    float4 sv[4][4];               // cached S0 values: [chunk][row]
    float acc[4] = {};
#pragma unroll
    for (int c = 0; c < 4; c++) {
        int j = c * 1024 + t * 4;
        float4 cv = *(const float4*)&cs[j];
        float rx = 1.f / cv.x, ry = 1.f / cv.y, rz = 1.f / cv.z, rw = 1.f / cv.w;
#pragma unroll
        for (int r = 0; r < 4; r++) {
            float4 s = *(const float4*)&S0[(size_t)(r0 + r) * NTGT + j];
            sv[c][r] = s;
            acc[r] += s.x * rx + s.y * ry + s.z * rz + s.w * rw;
        }
    }
    __shared__ float red[8][4];
    __shared__ float su[4];
    int w = t >> 5, ln = t & 31;
#pragma unroll
    for (int r = 0; r < 4; r++) {
        float a = acc[r];
#pragma unroll
        for (int o = 16; o; o >>= 1) a += __shfl_xor_sync(0xffffffffu, a, o);
        if (ln == 0) red[w][r] = a;
    }
    __syncthreads();
    if (t < 4) {
        float s = 0.f;
#pragma unroll
        for (int w2 = 0; w2 < 8; w2++) s += red[w2][t];
        su[t] = 1.f / s;
    }
    __syncthreads();
    float u0 = su[0], u1 = su[1], u2 = su[2], u3 = su[3];
#pragma unroll
    for (int c = 0; c < 4; c++) {
        int j = c * 1024 + t * 4;
        float4 ca;
        ca.x = u0 * sv[c][0].x + u1 * sv[c][1].x + u2 * sv[c][2].x + u3 * sv[c][3].x;
        ca.y = u0 * sv[c][0].y + u1 * sv[c][1].y + u2 * sv[c][2].y + u3 * sv[c][3].y;
        ca.z = u0 * sv[c][0].z + u1 * sv[c][1].z + u2 * sv[c][2].z + u3 * sv[c][3].z;
        ca.w = u0 * sv[c][0].w + u1 * sv[c][1].w + u2 * sv[c][2].w + u3 * sv[c][3].w;
        asm volatile("red.global.add.v4.f32 [%0], {%1,%2,%3,%4};"
                     :: "l"(&csn[j]), "f"(ca.x), "f"(ca.y), "f"(ca.z), "f"(ca.w) : "memory");
    }
}

// ---------------- final sinkhorn row pass + output write (single S0 read, 4 rows/block) ----------------
__global__ __launch_bounds__(256, 1) void sink_rowout_kernel(
    const float* __restrict__ cs, float* __restrict__ out, const float* __restrict__ S0)
{
    int r0 = blockIdx.x * 4, t = threadIdx.x;
    float4 sv[4][4];
    float4 rv[4];
    float acc[4] = {};
#pragma unroll
    for (int c = 0; c < 4; c++) {
        int j = c * 1024 + t * 4;
        float4 cv = *(const float4*)&cs[j];
        rv[c] = make_float4(1.f / cv.x, 1.f / cv.y, 1.f / cv.z, 1.f / cv.w);
#pragma unroll
        for (int r = 0; r < 4; r++) {
            float4 s = *(const float4*)&S0[(size_t)(r0 + r) * NTGT + j];
            sv[c][r] = s;
            acc[r] += s.x * rv[c].x + s.y * rv[c].y + s.z * rv[c].z + s.w * rv[c].w;
        }
    }
    __shared__ float red[8][4];
    __shared__ float su[4];
    int w = t >> 5, ln = t & 31;
#pragma unroll
    for (int r = 0; r < 4; r++) {
        float a = acc[r];
#pragma unroll
        for (int o = 16; o; o >>= 1) a += __shfl_xor_sync(0xffffffffu, a, o);
        if (ln == 0) red[w][r] = a;
    }
    __syncthreads();
    if (t < 4) {
        float s = 0.f;
#pragma unroll
        for (int w2 = 0; w2 < 8; w2++) s += red[w2][t];
        su[t] = 1.f / s;
    }
    __syncthreads();
    float u[4];
#pragma unroll
    for (int r = 0; r < 4; r++) u[r] = su[r];
#pragma unroll
    for (int c = 0; c < 4; c++) {
        int j = c * 1024 + t * 4;
#pragma unroll
        for (int r = 0; r < 4; r++) {
            float4 s = sv[c][r];
            float4 o;
            o.x = u[r] * s.x * rv[c].x;
            o.y = u[r] * s.y * rv[c].y;
            o.z = u[r] * s.z * rv[c].z;
            o.w = u[r] * s.w * rv[c].w;
            *(float4*)&out[(size_t)(r0 + r) * NTGT + j] = o;
        }
    }
}

// ---------------- host orchestration ----------------
extern "C" void kernel_launch(void* const* d_in, const int* in_sizes, int n_in,
                              void* d_out, int out_size)
{
    const float* x_s = (const float*)d_in[0];
    const float* x_t = (const float*)d_in[1];
    const int* edges = (const int*)d_in[2];
    const int* edget = (const int*)d_in[3];
    const float* W1_0 = (const float*)d_in[4];
    const float* W2_0 = (const float*)d_in[5];
    const float* Wr_0 = (const float*)d_in[6];
    const float* br_0 = (const float*)d_in[7];
    const float* W1_1 = (const float*)d_in[8];
    const float* W2_1 = (const float*)d_in[9];
    const float* Wr_1 = (const float*)d_in[10];
    const float* br_1 = (const float*)d_in[11];
    const float* W1_2 = (const float*)d_in[12];
    const float* W2_2 = (const float*)d_in[13];
    const float* Wr_2 = (const float*)d_in[14];
    const float* br_2 = (const float*)d_in[15];
    const float* final_w = (const float*)d_in[16];
    const float* final_b = (const float*)d_in[17];
    int ES = in_sizes[2] / 2;
    int ET = in_sizes[3] / 2;

    float *cat, *feat, *S0, *cs;
    __nv_bfloat16 *cat_hi, *cat_lo, *hc_hi, *hc_lo, *ft_hi, *ft_lo, *wt_hi, *wt_lo;
    cudaGetSymbolAddress((void**)&cat, g_cat);
    cudaGetSymbolAddress((void**)&cat_hi, g_cat_hi);
    cudaGetSymbolAddress((void**)&cat_lo, g_cat_lo);
    cudaGetSymbolAddress((void**)&hc_hi, g_hc_hi);
    cudaGetSymbolAddress((void**)&hc_lo, g_hc_lo);
    cudaGetSymbolAddress((void**)&feat, g_feat);
    cudaGetSymbolAddress((void**)&ft_hi, g_ft_hi);
    cudaGetSymbolAddress((void**)&ft_lo, g_ft_lo);
    cudaGetSymbolAddress((void**)&wt_hi, g_wt_hi);
    cudaGetSymbolAddress((void**)&wt_lo, g_wt_lo);
    cudaGetSymbolAddress((void**)&S0, g_S0);
    cudaGetSymbolAddress((void**)&cs, g_cs);

    cudaFuncSetAttribute(gemm_kernel<0>, cudaFuncAttributeMaxDynamicSharedMemorySize, SMEM_GEMM);
    cudaFuncSetAttribute(gemm_kernel<1>, cudaFuncAttributeMaxDynamicSharedMemorySize, SMEM_GEMM);
    cudaFuncSetAttribute(gemm_kernel<2>, cudaFuncAttributeMaxDynamicSharedMemorySize, SMEM_GEMM);

    // setup: weights + adjacency lists
    pack_wt_kernel<<<(720896 + 255) / 256, 256>>>(W1_0, W2_0, Wr_0, W1_1, W2_1, Wr_1,
                                                  W1_2, W2_2, Wr_2, final_w);
    init_kernel<<<NROW / 256, 256>>>();
    fill_kernel<<<(ES + ET + 255) / 256, 256>>>(edges, edges + ES, ES, edget, edget + ET, ET);
    recip_kernel<<<NROW / 256, 256>>>();

    const float* brs[3] = {br_0, br_1, br_2};
    const int woff[3] = {0, 98304, 294912};

    for (int l = 0; l < 3; l++) {
        int fan = l ? 256 : 128;
        int fan3 = 3 * fan;
        if (l == 0) gather0_kernel<<<NROW / 2, 256>>>(x_s, x_t);
        else gather12_kernel<<<NROW, 256>>>(cat + 128 + (l - 1) * 256);
        gemm_kernel<0><<<dim3(NROW / 128, 2), 256, SMEM_GEMM>>>(
            hc_hi, hc_lo, fan3, wt_hi + woff[l], wt_lo + woff[l], fan3, fan3, brs[l],
            cat + 128 + l * 256, cat_hi + 128 + l * 256, cat_lo + 128 + l * 256, CATW, nullptr);
    }
    // final linear
    gemm_kernel<1><<<dim3(NROW / 128, 2), 256, SMEM_GEMM>>>(
        cat_hi, cat_lo, CATW, wt_hi + 491520, wt_lo + 491520, CATW, CATW, final_b,
        feat, nullptr, nullptr, 256, nullptr);
    l2norm_split_kernel<<<NROW, 256>>>();

    // match matrix: exp epilogue + fused first col-normalization sums into cs0
    gemm_kernel<2><<<dim3(NTGT / 128, NTGT / 128), 256, SMEM_GEMM>>>(
        ft_hi, ft_lo, 256, ft_hi + (size_t)TOFF * 256, ft_lo + (size_t)TOFF * 256, 256, 256,
        nullptr, S0, nullptr, nullptr, NTGT, cs);

    // sinkhorn: fused (row+col) x4, then row+out (each pass reads S0 once)
    sink_rowcol_kernel<<<NTGT / 4, 256>>>(cs + 0 * NTGT, cs + 1 * NTGT, S0);
    sink_rowcol_kernel<<<NTGT / 4, 256>>>(cs + 1 * NTGT, cs + 2 * NTGT, S0);
    sink_rowcol_kernel<<<NTGT / 4, 256>>>(cs + 2 * NTGT, cs + 3 * NTGT, S0);
    sink_rowcol_kernel<<<NTGT / 4, 256>>>(cs + 3 * NTGT, cs + 4 * NTGT, S0);
    sink_rowout_kernel<<<NSRC / 4, 256>>>(cs + 4 * NTGT, (float*)d_out, S0);
}